// round 2
// baseline (speedup 1.0000x reference)
#include <cuda_runtime.h>
#include <cuda_bf16.h>
#include <math.h>

#define BINS  10
#define BLOCK 256
#define GRID  1184   // 148 SMs * 8

// Per-block partials — written unconditionally by every block every launch,
// so no zeroing kernel and no atomics are needed. Graph-replay deterministic.
__device__ float g_psum[GRID * BINS];
__device__ float g_pcnt[GRID * BINS];

__device__ __forceinline__ void process_elem(float p, float t, float w,
                                             float* s_sum, float* s_cnt, int tid) {
    if (w > 0.0f) {
        // target is binary: fold to q = p*(1-2t) -> g = sigmoid(q), bce = softplus(q)
        float q  = (t > 0.0f) ? -p : p;
        float aq = fabsf(q);
        float e  = __expf(-aq);          // exp(-|q|)
        float r  = __frcp_rn(1.0f + e);  // 1/(1+e)
        float g  = (q >= 0.0f) ? r : e * r;   // sigmoid(q) = |sigmoid(p)-t|
        int bin  = (int)(g * 10.0f);
        bin = bin > (BINS - 1) ? (BINS - 1) : bin;
        // bce = max(q,0) + log(1+e) = max(q,0) - log(r)
        float bce = fmaxf(q, 0.0f) - __logf(r);
        s_sum[bin * BLOCK + tid] += bce;
        s_cnt[bin * BLOCK + tid] += 1.0f;
    }
}

__global__ void __launch_bounds__(BLOCK)
ghm_main(const float* __restrict__ pred,
         const float* __restrict__ target,
         const float* __restrict__ lw,
         int n) {
    // Per-thread private histogram columns: [bin][tid] -> bank = tid%32, conflict-free.
    __shared__ float s_sum[BINS * BLOCK];
    __shared__ float s_cnt[BINS * BLOCK];

    const int tid = threadIdx.x;
#pragma unroll
    for (int b = 0; b < BINS; b++) {
        s_sum[b * BLOCK + tid] = 0.0f;
        s_cnt[b * BLOCK + tid] = 0.0f;
    }
    __syncthreads();

    const int n4 = n >> 2;
    const float4* __restrict__ p4 = (const float4*)pred;
    const float4* __restrict__ t4 = (const float4*)target;
    const float4* __restrict__ w4 = (const float4*)lw;

    const int stride = GRID * BLOCK;
    int i = blockIdx.x * BLOCK + tid;

    // 2x unrolled: 6 front-batched LDG.128 (streaming, evict-first) per iter.
    for (; i + stride < n4; i += 2 * stride) {
        float4 pa = __ldcs(&p4[i]);
        float4 ta = __ldcs(&t4[i]);
        float4 wa = __ldcs(&w4[i]);
        float4 pb = __ldcs(&p4[i + stride]);
        float4 tb = __ldcs(&t4[i + stride]);
        float4 wb = __ldcs(&w4[i + stride]);
        process_elem(pa.x, ta.x, wa.x, s_sum, s_cnt, tid);
        process_elem(pa.y, ta.y, wa.y, s_sum, s_cnt, tid);
        process_elem(pa.z, ta.z, wa.z, s_sum, s_cnt, tid);
        process_elem(pa.w, ta.w, wa.w, s_sum, s_cnt, tid);
        process_elem(pb.x, tb.x, wb.x, s_sum, s_cnt, tid);
        process_elem(pb.y, tb.y, wb.y, s_sum, s_cnt, tid);
        process_elem(pb.z, tb.z, wb.z, s_sum, s_cnt, tid);
        process_elem(pb.w, tb.w, wb.w, s_sum, s_cnt, tid);
    }
    for (; i < n4; i += stride) {
        float4 p = __ldcs(&p4[i]);
        float4 t = __ldcs(&t4[i]);
        float4 w = __ldcs(&w4[i]);
        process_elem(p.x, t.x, w.x, s_sum, s_cnt, tid);
        process_elem(p.y, t.y, w.y, s_sum, s_cnt, tid);
        process_elem(p.z, t.z, w.z, s_sum, s_cnt, tid);
        process_elem(p.w, t.w, w.w, s_sum, s_cnt, tid);
    }
    // Scalar tail (n not multiple of 4) — block 0 only.
    if (blockIdx.x == 0) {
        for (int j = (n4 << 2) + tid; j < n; j += BLOCK)
            process_elem(pred[j], target[j], lw[j], s_sum, s_cnt, tid);
    }

    __syncthreads();
    // Tree-reduce each bin's 256 partials.
    for (int s = BLOCK / 2; s > 0; s >>= 1) {
        if (tid < s) {
#pragma unroll
            for (int b = 0; b < BINS; b++) {
                s_sum[b * BLOCK + tid] += s_sum[b * BLOCK + tid + s];
                s_cnt[b * BLOCK + tid] += s_cnt[b * BLOCK + tid + s];
            }
        }
        __syncthreads();
    }
    if (tid < BINS) {
        // Unconditional per-block write: no zeroing, no atomics.
        g_psum[blockIdx.x * BINS + tid] = s_sum[tid * BLOCK];
        g_pcnt[blockIdx.x * BINS + tid] = s_cnt[tid * BLOCK];  // <= ~28K, fp32-exact
    }
}

__global__ void __launch_bounds__(32 * BINS)
ghm_final(float* __restrict__ out) {
    __shared__ double ssum[BINS];
    __shared__ double scnt[BINS];
    const int wid  = threadIdx.x >> 5;
    const int lane = threadIdx.x & 31;

    if (wid < BINS) {
        double s = 0.0, c = 0.0;
        for (int b = lane; b < GRID; b += 32) {
            s += (double)g_psum[b * BINS + wid];
            c += (double)g_pcnt[b * BINS + wid];
        }
#pragma unroll
        for (int o = 16; o > 0; o >>= 1) {
            s += __shfl_down_sync(0xFFFFFFFFu, s, o);
            c += __shfl_down_sync(0xFFFFFFFFu, c, o);
        }
        if (lane == 0) { ssum[wid] = s; scnt[wid] = c; }
    }
    __syncthreads();

    if (threadIdx.x == 0) {
        double acc = 0.0;
        int ne = 0;
#pragma unroll
        for (int b = 0; b < BINS; b++) {
            double c = scnt[b];
            if (c > 0.0) { acc += ssum[b] / c; ne++; }
        }
        float loss = (ne > 0) ? (float)(acc / (double)ne) : 0.0f;
        out[0] = loss * 1.0f;  // LOSS_WEIGHT
    }
}

extern "C" void kernel_launch(void* const* d_in, const int* in_sizes, int n_in,
                              void* d_out, int out_size) {
    const float* pred   = (const float*)d_in[0];
    const float* target = (const float*)d_in[1];
    const float* lw     = (const float*)d_in[2];
    float* out = (float*)d_out;
    int n = in_sizes[0];

    ghm_main<<<GRID, BLOCK>>>(pred, target, lw, n);
    ghm_final<<<1, 32 * BINS>>>(out);
}